// round 15
// baseline (speedup 1.0000x reference)
#include <cuda_runtime.h>
#include <cuda_fp16.h>
#include <math.h>
#include <stdint.h>

// ---------------- problem dims ----------------
constexpr int Bb = 32, Cc = 512, Hh = 24, Ww = 24;
constexpr int Ll = Hh * Ww;          // 576
constexpr int Dd = 1024, Kk = 4, Nst = 4, Rr = 32, MH = 2048;
constexpr int BL = Bb * Ll;          // 18432
constexpr int XDP = 256;             // padded x_proj output stride (160 used)

// ---------------- fp32 scratch ----------------
constexpr size_t OFF_XT     = 0;
constexpr size_t OFF_XDBL   = OFF_XT     + (size_t)BL * Cc;      // xd_pad [BL,256]
constexpr size_t OFF_XRES   = OFF_XDBL   + (size_t)BL * XDP;
constexpr size_t OFF_CONVWT = OFF_XRES   + (size_t)BL * Cc;
constexpr size_t TOTF       = OFF_CONVWT + (size_t)9 * Dd;

__device__ __align__(128) float g_buf[TOTF];
#define BUF(off) (g_buf + (off))

// ---------------- fp16 scratch ----------------
constexpr size_t HH_H      = 0;
constexpr size_t HH_XZ     = HH_H      + (size_t)BL * Cc;
constexpr size_t HH_XC     = HH_XZ     + (size_t)BL * 2 * Dd;
constexpr size_t HH_DTS    = HH_XC     + (size_t)BL * Dd;
constexpr size_t HH_YS     = HH_DTS    + (size_t)Kk * BL * Dd;
constexpr size_t HH_YG     = HH_YS     + (size_t)Kk * BL * Dd;
constexpr size_t HH_M1     = HH_YG     + (size_t)BL * Dd;
constexpr size_t HH_MH     = HH_M1     + (size_t)BL * Cc;
constexpr size_t HH_WIP    = HH_MH     + (size_t)BL * MH;
constexpr size_t HH_WOP    = HH_WIP    + (size_t)2 * Dd * Cc;
constexpr size_t HH_WF1    = HH_WOP    + (size_t)Cc * Dd;
constexpr size_t HH_WF2    = HH_WF1    + (size_t)MH * Cc;
constexpr size_t HH_WDT    = HH_WF2    + (size_t)Cc * MH;
constexpr size_t HH_WXP    = HH_WDT    + (size_t)Kk * Dd * Rr;
constexpr size_t HH_ADT    = HH_WXP    + (size_t)XDP * Dd;
constexpr size_t TOTH      = HH_ADT    + (size_t)Kk * BL * Rr;

__device__ __align__(128) __half g_hh[TOTH];

// ---------------- helpers ----------------
__device__ __forceinline__ uint32_t s2u(const void* p) {
    uint32_t a;
    asm("{ .reg .u64 t; cvta.to.shared.u64 t, %1; cvt.u32.u64 %0, t; }" : "=r"(a) : "l"(p));
    return a;
}
__device__ __forceinline__ void cpasync16(uint32_t dst, const void* src) {
    asm volatile("cp.async.cg.shared.global [%0], [%1], 16;" :: "r"(dst), "l"(src));
}
__device__ __forceinline__ void cpcommit() { asm volatile("cp.async.commit_group;" ::: "memory"); }
template <int N>
__device__ __forceinline__ void cpwaitN() {
    asm volatile("cp.async.wait_group %0;" :: "n"(N) : "memory");
}
__device__ __forceinline__ void ldm_x4(uint32_t* d, uint32_t addr) {
    asm volatile("ldmatrix.sync.aligned.m8n8.x4.shared.b16 {%0,%1,%2,%3}, [%4];"
                 : "=r"(d[0]), "=r"(d[1]), "=r"(d[2]), "=r"(d[3]) : "r"(addr));
}
__device__ __forceinline__ void mma_f16(float* c, const uint32_t* a, const uint32_t* b) {
    asm volatile(
        "mma.sync.aligned.m16n8k16.row.col.f32.f16.f16.f32 "
        "{%0,%1,%2,%3}, {%4,%5,%6,%7}, {%8,%9}, {%0,%1,%2,%3};"
        : "+f"(c[0]), "+f"(c[1]), "+f"(c[2]), "+f"(c[3])
        : "r"(a[0]), "r"(a[1]), "r"(a[2]), "r"(a[3]), "r"(b[0]), "r"(b[1]));
}
__device__ __forceinline__ float gelu_tanh(float x) {
    return 0.5f * x * (1.f + tanhf(0.7978845608028654f * (x + 0.044715f * x * x * x)));
}
__device__ __forceinline__ int permL(int k, int l) {
    int ll = (k & 2) ? (Ll - 1 - l) : l;
    if (k & 1) ll = (ll % Hh) * Ww + (ll / Hh);
    return ll;
}
// block-wide sum of (s, s2) via warp shuffles; 256 threads; returns via smem bc[0..1]=(mu,inv)
__device__ __forceinline__ void blk_stats(float s, float s2, float invW, float* bc) {
    __shared__ float ps[8], ps2[8];
    const int lane = threadIdx.x & 31, wd = threadIdx.x >> 5;
#pragma unroll
    for (int o = 16; o > 0; o >>= 1) {
        s  += __shfl_xor_sync(0xffffffffu, s, o);
        s2 += __shfl_xor_sync(0xffffffffu, s2, o);
    }
    if (lane == 0) { ps[wd] = s; ps2[wd] = s2; }
    __syncthreads();
    if (threadIdx.x == 0) {
        float ts = 0.f, ts2 = 0.f;
#pragma unroll
        for (int i = 0; i < 8; i++) { ts += ps[i]; ts2 += ps2[i]; }
        const float mu = ts * invW;
        bc[0] = mu;
        bc[1] = rsqrtf(fmaxf(ts2 * invW - mu * mu, 0.f) + 1e-5f);
    }
    __syncthreads();
}

// ---------------- fp16 tensor-core GEMM, templated K-chunk (BK 32 or 64) ----------------
// C[128x128] = A @ (sum_p B_p)^T. NP passes over B. fp32 accum. 256 thr, 2x4 warps, 64x32 tile.
// EPI 0: +bias->fp32  1: +bias+res->fp32  2: gelu(+bias)->fp16  3: +bias->fp16
// EPI 4: +bias+res -> transposed (B,C,L) fp32 out   5: softplus(+bias)->fp16
#define N_STAGES(BK)  ((BK) == 64 ? 3 : 4)
#define GEMM_SMEM_BK(BK) (N_STAGES(BK) * 128 * (BK) * 2 * 2)

template <int BK>
__device__ __forceinline__ uint32_t swz(int row, int c) {
    if (BK == 64) return (uint32_t)(row * 128 + (((c ^ (row & 7))) << 4));
    return (uint32_t)(row * 64 + (((c + (row >> 1)) & 3) << 4));
}

template <int EPI, int NP, int BK>
__global__ __launch_bounds__(256, 2)
void k_gemm(const __half* __restrict__ A,
            const __half* __restrict__ Bhi, const __half* __restrict__ Blo,
            const float* __restrict__ bias, const float* __restrict__ res,
            float* __restrict__ outF, __half* __restrict__ outH,
            int Nn, int Kd, long sA, long sB, long sBias, long sOut) {
    constexpr int CH = BK / 8;
    constexpr int ROWB = BK * 2;
    constexpr int STG = 128 * ROWB;
    constexpr int STAGE = 2 * STG;
    constexpr int NSTG = N_STAGES(BK);
    constexpr int PFD = NSTG - 1;

    extern __shared__ __align__(128) char sm[];
    const int tid = threadIdx.x, lane = tid & 31, wid = tid >> 5;
    const int wm = wid & 1, wn = wid >> 1;
    const int bm = blockIdx.x * 128, bn = blockIdx.y * 128;
    const long kz = blockIdx.z;
    A += kz * sA; Bhi += kz * sB;
    if (bias) bias += kz * sBias;
    if (outH) outH += kz * sOut;
    if (outF) outF += kz * sOut;

    const int nk = Kd / BK, T = NP * nk;
    const __half* pb[2] = {Bhi, Blo};
    const uint32_t smBase = s2u(sm);

    auto issue = [&](int it, int stg) {
        const int p = (NP == 2) ? (it >= nk) : 0;
        const int kc = (it - p * nk) * BK;
        const uint32_t st = smBase + (uint32_t)stg * STAGE;
        const __half* Bp = pb[p];
#pragma unroll
        for (int i = 0; i < 128 * CH / 256; i++) {
            const int g = tid + i * 256;
            const int row = g / CH, c = g % CH;
            const uint32_t sw = swz<BK>(row, c);
            cpasync16(st + sw,       A  + (size_t)(bm + row) * Kd + kc + c * 8);
            cpasync16(st + STG + sw, Bp + (size_t)(bn + row) * Kd + kc + c * 8);
        }
    };

    float acc[4][4][4];
#pragma unroll
    for (int i = 0; i < 4; i++)
#pragma unroll
        for (int j = 0; j < 4; j++)
#pragma unroll
            for (int q = 0; q < 4; q++) acc[i][j][q] = 0.f;

#pragma unroll
    for (int i = 0; i < PFD; i++) { if (i < T) issue(i, i); cpcommit(); }

    int stI = PFD % NSTG, stC = 0;
    for (int it = 0; it < T; it++) {
        cpwaitN<NSTG - 2>();
        __syncthreads();
        if (it + PFD < T) issue(it + PFD, stI);
        cpcommit();
        const uint32_t aB = smBase + (uint32_t)stC * STAGE;
        const uint32_t bB = aB + STG;
#pragma unroll
        for (int s16 = 0; s16 < BK / 16; s16++) {
            uint32_t af[4][4], bf4[2][4];
#pragma unroll
            for (int mi = 0; mi < 4; mi++) {
                const int r = wm * 64 + mi * 16 + (lane & 15);
                const int c = 2 * s16 + (lane >> 4);
                ldm_x4(af[mi], aB + swz<BK>(r, c));
            }
#pragma unroll
            for (int nj = 0; nj < 2; nj++) {
                const int r = wn * 32 + (nj * 2 + (lane >> 4)) * 8 + (lane & 7);
                const int c = 2 * s16 + ((lane >> 3) & 1);
                ldm_x4(bf4[nj], bB + swz<BK>(r, c));
            }
#pragma unroll
            for (int mi = 0; mi < 4; mi++)
#pragma unroll
                for (int nj = 0; nj < 2; nj++) {
                    mma_f16(acc[mi][nj * 2 + 0], af[mi], &bf4[nj][0]);
                    mma_f16(acc[mi][nj * 2 + 1], af[mi], &bf4[nj][2]);
                }
        }
        stI = (stI + 1 == NSTG) ? 0 : stI + 1;
        stC = (stC + 1 == NSTG) ? 0 : stC + 1;
    }

    if (EPI == 4) {
        float* smf = (float*)sm;
        const bool nostrad = (bm % Ll) + 128 <= Ll;
        const int bq0 = bm / Ll, l0 = bm % Ll;
#pragma unroll
        for (int hn = 0; hn < 2; hn++) {
            __syncthreads();
            if ((wn >> 1) == hn) {
#pragma unroll
                for (int mi = 0; mi < 4; mi++)
#pragma unroll
                    for (int ni = 0; ni < 4; ni++) {
                        const int nL = (wn & 1) * 32 + ni * 8 + (lane & 3) * 2;
                        const int n = bn + hn * 64 + nL;
                        const float b0v = __ldg(bias + n), b1v = __ldg(bias + n + 1);
#pragma unroll
                        for (int h = 0; h < 2; h++) {
                            const int mL = wm * 64 + mi * 16 + (lane >> 2) + h * 8;
                            const int m = bm + mL;
                            const float2 rv = *(const float2*)(res + (size_t)m * Nn + n);
                            smf[nL * 132 + mL]       = acc[mi][ni][h * 2 + 0] + b0v + rv.x;
                            smf[(nL + 1) * 132 + mL] = acc[mi][ni][h * 2 + 1] + b1v + rv.y;
                        }
                    }
            }
            __syncthreads();
#pragma unroll
            for (int j = 0; j < 8; j++) {
                const int nr = wid * 8 + j;
                const int ng = bn + hn * 64 + nr;
                const float4 v = *(const float4*)&smf[nr * 132 + lane * 4];
                if (nostrad) {
                    *(float4*)&outF[((size_t)bq0 * Cc + ng) * Ll + l0 + lane * 4] = v;
                } else {
                    const float vv[4] = {v.x, v.y, v.z, v.w};
#pragma unroll
                    for (int q = 0; q < 4; q++) {
                        const int m = bm + lane * 4 + q;
                        outF[((size_t)(m / Ll) * Cc + ng) * Ll + (m % Ll)] = vv[q];
                    }
                }
            }
        }
        return;
    }

#pragma unroll
    for (int mi = 0; mi < 4; mi++) {
#pragma unroll
        for (int ni = 0; ni < 4; ni++) {
            const int n = bn + wn * 32 + ni * 8 + (lane & 3) * 2;
            const float b0v = bias ? __ldg(bias + n) : 0.f;
            const float b1v = bias ? __ldg(bias + n + 1) : 0.f;
#pragma unroll
            for (int h = 0; h < 2; h++) {
                const int m = bm + wm * 64 + mi * 16 + (lane >> 2) + h * 8;
                float v0 = acc[mi][ni][h * 2 + 0] + b0v;
                float v1 = acc[mi][ni][h * 2 + 1] + b1v;
                if (EPI == 1) {
                    const float2 rv = *(const float2*)(res + (size_t)m * Nn + n);
                    v0 += rv.x; v1 += rv.y;
                }
                if (EPI == 2) { v0 = gelu_tanh(v0); v1 = gelu_tanh(v1); }
                if (EPI == 5) {
                    v0 = (v0 > 20.f) ? v0 : log1pf(__expf(v0));
                    v1 = (v1 > 20.f) ? v1 : log1pf(__expf(v1));
                }
                if (EPI == 2 || EPI == 3 || EPI == 5) {
                    __half2 hp; hp.x = __float2half(v0); hp.y = __float2half(v1);
                    *(__half2*)(outH + (size_t)m * Nn + n) = hp;
                } else {
                    *(float2*)(outF + (size_t)m * Nn + n) = make_float2(v0, v1);
                }
            }
        }
    }
}

// ---------------- fused: xt = sum of 3 p2t inputs (fp32 out) + LN1 -> fp16 h ----------------
__global__ void k_fuseln(const float* __restrict__ x1, const float* __restrict__ x2,
                         const float* __restrict__ x3, const float* __restrict__ w,
                         const float* __restrict__ bvec,
                         float* __restrict__ xt, __half* __restrict__ ho) {
    __shared__ float t[Cc * 9];
    const int blk = blockIdx.x;
    const int b = blk / (Ll / 8);
    const int l0 = (blk % (Ll / 8)) * 8;
    const int tid = threadIdx.x;

#pragma unroll
    for (int p = 0; p < 4; p++) {
        const int idx = tid + p * 256;
        const int c = idx >> 1, half = idx & 1;
        const size_t g = ((size_t)b * Cc + c) * Ll + l0 + half * 4;
        const float4 a = *(const float4*)(x1 + g);
        const float4 b2 = *(const float4*)(x2 + g);
        const float4 c2 = *(const float4*)(x3 + g);
        float* dst = t + c * 9 + half * 4;
        dst[0] = a.x + b2.x + c2.x;
        dst[1] = a.y + b2.y + c2.y;
        dst[2] = a.z + b2.z + c2.z;
        dst[3] = a.w + b2.w + c2.w;
    }
    __syncthreads();

    const int lane = tid & 31, wd = tid >> 5;
    float v[16];
    float s = 0.f, s2 = 0.f;
#pragma unroll
    for (int i = 0; i < 16; i++) {
        const int c = lane + i * 32;
        v[i] = t[c * 9 + wd];
        s += v[i]; s2 += v[i] * v[i];
    }
#pragma unroll
    for (int o = 16; o > 0; o >>= 1) {
        s  += __shfl_xor_sync(0xffffffffu, s, o);
        s2 += __shfl_xor_sync(0xffffffffu, s2, o);
    }
    const float mu = s * (1.f / Cc);
    const float inv = rsqrtf(fmaxf(s2 * (1.f / Cc) - mu * mu, 0.f) + 1e-5f);

    const size_t row = (size_t)b * Ll + l0 + wd;
#pragma unroll
    for (int i = 0; i < 16; i++) {
        const int c = lane + i * 32;
        xt[row * Cc + c] = v[i];
        ho[row * Cc + c] = __float2half((v[i] - mu) * inv * w[c] + bvec[c]);
    }
}

// ---------------- LayerNorm(512) -> fp16 (256 threads, shuffle reduction) ----------------
__global__ void k_ln_h(const float* __restrict__ in, const float* __restrict__ w,
                       const float* __restrict__ bvec, __half* __restrict__ ho) {
    __shared__ float bc[2];
    const size_t row = blockIdx.x;
    const float* x = in + row * Cc;
    const int tid = threadIdx.x;

    const float a0 = x[tid], a1 = x[tid + 256];
    blk_stats(a0 + a1, a0 * a0 + a1 * a1, 1.f / Cc, bc);
    const float mu = bc[0], inv = bc[1];

    ho[row * Cc + tid]       = __float2half((a0 - mu) * inv * w[tid] + bvec[tid]);
    ho[row * Cc + tid + 256] = __float2half((a1 - mu) * inv * w[tid + 256] + bvec[tid + 256]);
}

// ---------------- all weight conversions in one kernel ----------------
constexpr int WN1 = 2 * Dd * Cc;
constexpr int WN2 = WN1 + Cc * Dd;
constexpr int WN3 = WN2 + MH * Cc;
constexpr int WN4 = WN3 + Cc * MH;
constexpr int WN5 = WN4 + Kk * Dd * Rr;
constexpr int WN6 = WN5 + 9 * Dd;
constexpr int WN7 = WN6 + XDP * Dd;

__global__ void k_wconv(const float* __restrict__ wip, const float* __restrict__ wop,
                        const float* __restrict__ wf1, const float* __restrict__ wf2,
                        const float* __restrict__ wdt, const float* __restrict__ cw,
                        const float* __restrict__ wxp) {
    const int i = blockIdx.x * 256 + threadIdx.x;
    __half* HB = g_hh;
    if (i < WN1) HB[HH_WIP + i] = __float2half(wip[i]);
    else if (i < WN2) HB[HH_WOP + (i - WN1)] = __float2half(wop[i - WN1]);
    else if (i < WN3) HB[HH_WF1 + (i - WN2)] = __float2half(wf1[i - WN2]);
    else if (i < WN4) HB[HH_WF2 + (i - WN3)] = __float2half(wf2[i - WN3]);
    else if (i < WN5) HB[HH_WDT + (i - WN4)] = __float2half(wdt[i - WN4]);
    else if (i < WN6) {
        const int j = (i - WN5) / Dd, d = (i - WN5) % Dd;
        BUF(OFF_CONVWT)[i - WN5] = cw[(size_t)d * 9 + j];
    } else if (i < WN7) {
        const int j = i - WN6;
        const int row = j >> 10;
        HB[HH_WXP + j] = (row < 160) ? __float2half(wxp[j]) : __float2half(0.f);
    }
}

// ---------------- depthwise 3x3 conv + SiLU (128 thr x 8 d, uint4 loads) ----------------
__global__ __launch_bounds__(128, 10)
void k_conv(const float* __restrict__ conv_b, const __half* __restrict__ xz,
            __half* __restrict__ xc) {
    const int bl = blockIdx.x;
    const int d = threadIdx.x * 8;          // 16B-aligned in fp16
    const int b = bl / Ll, l = bl % Ll;
    const int h = l / Ww, w = l % Ww;
    const float* cw = BUF(OFF_CONVWT);

    float acc[8];
    {
        const float4 b0 = *(const float4*)(conv_b + d);
        const float4 b1 = *(const float4*)(conv_b + d + 4);
        acc[0] = b0.x; acc[1] = b0.y; acc[2] = b0.z; acc[3] = b0.w;
        acc[4] = b1.x; acc[5] = b1.y; acc[6] = b1.z; acc[7] = b1.w;
    }
    const __half* base = xz + (size_t)b * Ll * 2 * Dd + d;
    const bool interior = (h > 0 && h < Hh - 1 && w > 0 && w < Ww - 1);

#pragma unroll
    for (int kh = -1; kh <= 1; kh++) {
        const int hh = h + kh;
        if (!interior && (hh < 0 || hh >= Hh)) continue;
#pragma unroll
        for (int kw = -1; kw <= 1; kw++) {
            const int ww2 = w + kw;
            if (!interior && (ww2 < 0 || ww2 >= Ww)) continue;
            const uint4 raw = *(const uint4*)(base + (size_t)(hh * Ww + ww2) * 2 * Dd);
            const __half2* hp = (const __half2*)&raw;
            const int wi = ((kh + 1) * 3 + kw + 1) * Dd + d;
            const float4 w0 = *(const float4*)(cw + wi);
            const float4 w1 = *(const float4*)(cw + wi + 4);
            const float2 v0 = __half22float2(hp[0]);
            const float2 v1 = __half22float2(hp[1]);
            const float2 v2 = __half22float2(hp[2]);
            const float2 v3 = __half22float2(hp[3]);
            acc[0] += v0.x * w0.x; acc[1] += v0.y * w0.y;
            acc[2] += v1.x * w0.z; acc[3] += v1.y * w0.w;
            acc[4] += v2.x * w1.x; acc[5] += v2.y * w1.y;
            acc[6] += v3.x * w1.z; acc[7] += v3.y * w1.w;
        }
    }
    uint4 oraw;
    __half2* op = (__half2*)&oraw;
#pragma unroll
    for (int i = 0; i < 4; i++) {
        const float a0 = acc[i * 2]     / (1.f + __expf(-acc[i * 2]));
        const float a1 = acc[i * 2 + 1] / (1.f + __expf(-acc[i * 2 + 1]));
        __half2 o; o.x = __float2half(a0); o.y = __float2half(a1);
        op[i] = o;
    }
    *(uint4*)(xc + (size_t)bl * Dd + d) = oraw;
}

// ---------------- gather dt-GEMM A operand ----------------
__global__ void k_adt(__half* __restrict__ adt) {
    const int idx = blockIdx.x * 256 + threadIdx.x;
    const int k = idx / (BL * Rr);
    const int rem = idx % (BL * Rr);
    const int bl = rem >> 5, r = rem & 31;
    const int b = bl / Ll, l = bl % Ll;
    const int pl = permL(k, l);
    adt[idx] = __float2half(BUF(OFF_XDBL)[((size_t)b * Ll + pl) * XDP + k * 40 + r]);
}

// ---------------- selective scan (fp16, fp32 state, 1-exp fast path, prefetch) ------------
__global__ void k_scan(const float* __restrict__ A_logs, const float* __restrict__ Ds,
                       const __half* __restrict__ xcg, const __half* __restrict__ dtsg,
                       __half* __restrict__ ysg) {
    const int blk = blockIdx.x;
    const int dc = blk & 3;
    const int kb = blk >> 2;
    const int b = kb % Bb;
    const int k = kb / Bb;
    const int d = dc * 256 + threadIdx.x;

    float Aa[Nst];
#pragma unroll
    for (int n = 0; n < Nst; n++) Aa[n] = -__expf(A_logs[((size_t)k * Dd + d) * Nst + n]);
    const float Dv = Ds[k * Dd + d];
    const float a0 = Aa[0];

    bool fast = true;
#pragma unroll
    for (int n = 1; n < Nst; n++)
        fast = fast && (fabsf(Aa[n] - (float)(n + 1) * a0) <= 1e-5f * (float)(n + 1) * fabsf(a0));

    const __half* xc = xcg + (size_t)b * Ll * Dd + d;
    const __half* dts = dtsg + ((size_t)k * BL + (size_t)b * Ll) * Dd + d;
    const float* xd = BUF(OFF_XDBL) + (size_t)b * Ll * XDP + k * 40 + Rr;
    __half* ys = ysg + ((size_t)k * BL + (size_t)b * Ll) * Dd + d;

    float hst[Nst] = {0.f, 0.f, 0.f, 0.f};

    // prefetch step 0
    int pl = permL(k, 0);
    float u = __half2float(xc[(size_t)pl * Dd]);
    float dt = __half2float(dts[0]);
    float4 Bv = *(const float4*)(xd + (size_t)pl * XDP);
    float4 Cv = *(const float4*)(xd + (size_t)pl * XDP + 4);

    if (fast) {
        for (int l = 0; l < Ll; l++) {
            // prefetch l+1 before compute (addresses independent of data)
            float un, dtn; float4 Bn, Cn;
            if (l + 1 < Ll) {
                const int pln = permL(k, l + 1);
                un = __half2float(xc[(size_t)pln * Dd]);
                dtn = __half2float(dts[(size_t)(l + 1) * Dd]);
                Bn = *(const float4*)(xd + (size_t)pln * XDP);
                Cn = *(const float4*)(xd + (size_t)pln * XDP + 4);
            }
            const float du = dt * u;
            const float e1 = __expf(dt * a0);
            const float e2 = e1 * e1;
            hst[0] = hst[0] * e1        + du * Bv.x;
            hst[1] = hst[1] * e2        + du * Bv.y;
            hst[2] = hst[2] * (e2 * e1) + du * Bv.z;
            hst[3] = hst[3] * (e2 * e2) + du * Bv.w;
            const float y = hst[0] * Cv.x + hst[1] * Cv.y + hst[2] * Cv.z + hst[3] * Cv.w;
            ys[(size_t)l * Dd] = __float2half(y + Dv * u);
            u = un; dt = dtn; Bv = Bn; Cv = Cn;
        }
    } else {
        for (int l = 0; l < Ll; l++) {
            float un, dtn; float4 Bn, Cn;
            if (l + 1 < Ll) {
                const int pln = permL(k, l + 1);
                un = __half2float(xc[(size_t)pln * Dd]);
                dtn = __half2float(dts[(size_t)(l + 1) * Dd]);
                Bn = *(const float4*)(xd + (size_t)pln * XDP);
                Cn = *(const float4*)(xd + (size_t)pln * XDP + 4);
            }
            const float du = dt * u;
            const float bArr[4] = {Bv.x, Bv.y, Bv.z, Bv.w};
            const float cArr[4] = {Cv.x, Cv.y, Cv.z, Cv.w};
            float y = 0.f;
#pragma unroll
            for (int n = 0; n < Nst; n++) {
                const float dA = __expf(dt * Aa[n]);
                hst[n] = hst[n] * dA + du * bArr[n];
                y += hst[n] * cArr[n];
            }
            ys[(size_t)l * Dd] = __float2half(y + Dv * u);
            u = un; dt = dtn; Bv = Bn; Cv = Cn;
        }
    }
}

// ---------------- cross-merge + out_norm LN + SiLU gate (256 thr, half2) ----------------
__global__ void k_merge(const float* __restrict__ onw, const float* __restrict__ onb,
                        const __half* __restrict__ ys, const __half* __restrict__ xz,
                        __half* __restrict__ yg) {
    __shared__ float bufr[Dd];
    __shared__ float bc[2];
    const int bl = blockIdx.x;
    const int b = bl / Ll, l = bl % Ll;
    const int h = l / Ww, w = l % Ww;
    const int lt = w * Hh + h;
    const int tid = threadIdx.x;

    const size_t r0 = (((size_t)(0 * Bb + b)) * Ll + l) * Dd;
    const size_t r1 = (((size_t)(1 * Bb + b)) * Ll + lt) * Dd;
    const size_t r2 = (((size_t)(2 * Bb + b)) * Ll + (Ll - 1 - l)) * Dd;
    const size_t r3 = (((size_t)(3 * Bb + b)) * Ll + (Ll - 1 - lt)) * Dd;

    float s = 0.f, s2 = 0.f;
#pragma unroll
    for (int it = 0; it < 2; it++) {
        const int d = (tid + it * 256) * 2;
        const float2 v0 = __half22float2(*(const __half2*)(ys + r0 + d));
        const float2 v1 = __half22float2(*(const __half2*)(ys + r1 + d));
        const float2 v2 = __half22float2(*(const __half2*)(ys + r2 + d));
        const float2 v3 = __half22float2(*(const __half2*)(ys + r3 + d));
        const float a = v0.x + v1.x + v2.x + v3.x;
        const float bb2 = v0.y + v1.y + v2.y + v3.y;
        bufr[d] = a; bufr[d + 1] = bb2;
        s += a + bb2; s2 += a * a + bb2 * bb2;
    }
    blk_stats(s, s2, 1.f / Dd, bc);
    const float mu = bc[0], inv = bc[1];

#pragma unroll
    for (int it = 0; it < 2; it++) {
        const int d = (tid + it * 256) * 2;
        const float2 zv = __half22float2(*(const __half2*)(xz + (size_t)bl * 2 * Dd + Dd + d));
        const float g0 = zv.x / (1.f + __expf(-zv.x));
        const float g1 = zv.y / (1.f + __expf(-zv.y));
        __half2 o;
        o.x = __float2half(((bufr[d] - mu) * inv * onw[d] + onb[d]) * g0);
        o.y = __float2half(((bufr[d + 1] - mu) * inv * onw[d + 1] + onb[d + 1]) * g1);
        *(__half2*)(yg + (size_t)bl * Dd + d) = o;
    }
}

// ---------------- launch ----------------
extern "C" void kernel_launch(void* const* d_in, const int* in_sizes, int n_in,
                              void* d_out, int out_size) {
    const float* x1        = (const float*)d_in[0];
    const float* x2        = (const float*)d_in[1];
    const float* x3        = (const float*)d_in[2];
    const float* ln1_w     = (const float*)d_in[3];
    const float* ln1_b     = (const float*)d_in[4];
    const float* in_proj_w = (const float*)d_in[5];
    const float* in_proj_b = (const float*)d_in[6];
    const float* conv_w    = (const float*)d_in[7];
    const float* conv_b    = (const float*)d_in[8];
    const float* x_proj_w  = (const float*)d_in[9];
    const float* dt_w      = (const float*)d_in[10];
    const float* dt_b      = (const float*)d_in[11];
    const float* A_logs    = (const float*)d_in[12];
    const float* Ds        = (const float*)d_in[13];
    const float* out_norm_w= (const float*)d_in[14];
    const float* out_norm_b= (const float*)d_in[15];
    const float* out_proj_w= (const float*)d_in[16];
    const float* out_proj_b= (const float*)d_in[17];
    const float* ln2_w     = (const float*)d_in[18];
    const float* ln2_b     = (const float*)d_in[19];
    const float* fc1_w     = (const float*)d_in[20];
    const float* fc1_b     = (const float*)d_in[21];
    const float* fc2_w     = (const float*)d_in[22];
    const float* fc2_b     = (const float*)d_in[23];
    float* out = (float*)d_out;

    void* pf = nullptr;  cudaGetSymbolAddress(&pf, g_buf);
    void* ph = nullptr;  cudaGetSymbolAddress(&ph, g_hh);
    float* F = (float*)pf;
    __half* HB = (__half*)ph;

    constexpr int SM64 = GEMM_SMEM_BK(64);
    constexpr int SM32 = GEMM_SMEM_BK(32);

    static bool attr_done = false;
    if (!attr_done) {
        cudaFuncSetAttribute(k_gemm<0, 1, 64>, cudaFuncAttributeMaxDynamicSharedMemorySize, SM64);
        cudaFuncSetAttribute(k_gemm<1, 1, 64>, cudaFuncAttributeMaxDynamicSharedMemorySize, SM64);
        cudaFuncSetAttribute(k_gemm<2, 1, 64>, cudaFuncAttributeMaxDynamicSharedMemorySize, SM64);
        cudaFuncSetAttribute(k_gemm<3, 1, 64>, cudaFuncAttributeMaxDynamicSharedMemorySize, SM64);
        cudaFuncSetAttribute(k_gemm<4, 1, 64>, cudaFuncAttributeMaxDynamicSharedMemorySize, SM64);
        cudaFuncSetAttribute(k_gemm<5, 1, 32>, cudaFuncAttributeMaxDynamicSharedMemorySize, SM32);
        attr_done = true;
    }

    // 1. all weight conversions
    k_wconv<<<(WN7 + 255) / 256, 256>>>(in_proj_w, out_proj_w, fc1_w, fc2_w, dt_w, conv_w, x_proj_w);
    // 2. fused 3-way fuse + LN1 -> xt fp32, h fp16
    k_fuseln<<<BL / 8, 256>>>(x1, x2, x3, ln1_w, ln1_b, F + OFF_XT, HB + HH_H);
    // 3. in_proj -> xz fp16
    k_gemm<3, 1, 64><<<dim3(BL / 128, 2 * Dd / 128), 256, SM64>>>(
        HB + HH_H, HB + HH_WIP, nullptr, in_proj_b, nullptr,
        nullptr, HB + HH_XZ, 2 * Dd, Cc, 0, 0, 0, 0);
    // 4. conv + silu -> xc fp16
    k_conv<<<BL, 128>>>(conv_b, HB + HH_XZ, HB + HH_XC);
    // 5. x_proj (single pass) -> xd fp32 [BL,256]
    k_gemm<0, 1, 64><<<dim3(BL / 128, XDP / 128), 256, SM64>>>(
        HB + HH_XC, HB + HH_WXP, nullptr, nullptr, nullptr,
        F + OFF_XDBL, nullptr, XDP, Dd, 0, 0, 0, 0);
    // 6. gather dt GEMM A operands
    k_adt<<<(Kk * BL * Rr) / 256, 256>>>(HB + HH_ADT);
    // 7. dt projection (batched): softplus(adt_k @ dt_w_k^T + dt_b_k)
    k_gemm<5, 1, 32><<<dim3(BL / 128, Dd / 128, Kk), 256, SM32>>>(
        HB + HH_ADT, HB + HH_WDT, nullptr, dt_b, nullptr,
        nullptr, HB + HH_DTS, Dd, Rr,
        (long)BL * Rr, (long)Dd * Rr, (long)Dd, (long)BL * Dd);
    // 8. selective scan -> ys fp16
    k_scan<<<Kk * Bb * 4, 256>>>(A_logs, Ds, HB + HH_XC, HB + HH_DTS, HB + HH_YS);
    // 9. merge + LN + gate -> yg fp16
    k_merge<<<BL, 256>>>(out_norm_w, out_norm_b, HB + HH_YS, HB + HH_XZ, HB + HH_YG);
    // 10. out_proj + residual(xt) -> xres fp32
    k_gemm<1, 1, 64><<<dim3(BL / 128, Cc / 128), 256, SM64>>>(
        HB + HH_YG, HB + HH_WOP, nullptr, out_proj_b, F + OFF_XT,
        F + OFF_XRES, nullptr, Cc, Dd, 0, 0, 0, 0);
    // 11. LN2 -> fp16
    k_ln_h<<<BL, 256>>>(F + OFF_XRES, ln2_w, ln2_b, HB + HH_M1);
    // 12. fc1 + gelu -> mh fp16
    k_gemm<2, 1, 64><<<dim3(BL / 128, MH / 128), 256, SM64>>>(
        HB + HH_M1, HB + HH_WF1, nullptr, fc1_b, nullptr,
        nullptr, HB + HH_MH, MH, Cc, 0, 0, 0, 0);
    // 13. fc2 + residual(xres) -> direct (B,C,H,W) output (fused token2patch)
    k_gemm<4, 1, 64><<<dim3(BL / 128, Cc / 128), 256, SM64>>>(
        HB + HH_MH, HB + HH_WF2, nullptr, fc2_b, F + OFF_XRES,
        out, nullptr, Cc, MH, 0, 0, 0, 0);
}

// round 16
// speedup vs baseline: 1.0651x; 1.0651x over previous
#include <cuda_runtime.h>
#include <cuda_fp16.h>
#include <math.h>
#include <stdint.h>

// ---------------- problem dims ----------------
constexpr int Bb = 32, Cc = 512, Hh = 24, Ww = 24;
constexpr int Ll = Hh * Ww;          // 576
constexpr int Dd = 1024, Kk = 4, Nst = 4, Rr = 32, MH = 2048;
constexpr int BL = Bb * Ll;          // 18432
constexpr int XDP = 256;             // padded x_proj output stride (160 used)

// ---------------- fp32 scratch ----------------
constexpr size_t OFF_XT     = 0;
constexpr size_t OFF_XDBL   = OFF_XT     + (size_t)BL * Cc;      // xd_pad [BL,256]
constexpr size_t OFF_XRES   = OFF_XDBL   + (size_t)BL * XDP;
constexpr size_t OFF_CONVWT = OFF_XRES   + (size_t)BL * Cc;
constexpr size_t TOTF       = OFF_CONVWT + (size_t)9 * Dd;

__device__ __align__(128) float g_buf[TOTF];
#define BUF(off) (g_buf + (off))

// ---------------- fp16 scratch ----------------
constexpr size_t HH_H      = 0;
constexpr size_t HH_XZ     = HH_H      + (size_t)BL * Cc;
constexpr size_t HH_XC     = HH_XZ     + (size_t)BL * 2 * Dd;
constexpr size_t HH_DTS    = HH_XC     + (size_t)BL * Dd;
constexpr size_t HH_YS     = HH_DTS    + (size_t)Kk * BL * Dd;
constexpr size_t HH_YG     = HH_YS     + (size_t)Kk * BL * Dd;
constexpr size_t HH_M1     = HH_YG     + (size_t)BL * Dd;
constexpr size_t HH_MH     = HH_M1     + (size_t)BL * Cc;
constexpr size_t HH_WIP    = HH_MH     + (size_t)BL * MH;
constexpr size_t HH_WOP    = HH_WIP    + (size_t)2 * Dd * Cc;
constexpr size_t HH_WF1    = HH_WOP    + (size_t)Cc * Dd;
constexpr size_t HH_WF2    = HH_WF1    + (size_t)MH * Cc;
constexpr size_t HH_WDT    = HH_WF2    + (size_t)Cc * MH;
constexpr size_t HH_WXP    = HH_WDT    + (size_t)Kk * Dd * Rr;
constexpr size_t HH_ADT    = HH_WXP    + (size_t)XDP * Dd;
constexpr size_t TOTH      = HH_ADT    + (size_t)Kk * BL * Rr;

__device__ __align__(128) __half g_hh[TOTH];

// ---------------- helpers ----------------
__device__ __forceinline__ uint32_t s2u(const void* p) {
    uint32_t a;
    asm("{ .reg .u64 t; cvta.to.shared.u64 t, %1; cvt.u32.u64 %0, t; }" : "=r"(a) : "l"(p));
    return a;
}
__device__ __forceinline__ void cpasync16(uint32_t dst, const void* src) {
    asm volatile("cp.async.cg.shared.global [%0], [%1], 16;" :: "r"(dst), "l"(src));
}
__device__ __forceinline__ void cpcommit() { asm volatile("cp.async.commit_group;" ::: "memory"); }
template <int N>
__device__ __forceinline__ void cpwaitN() {
    asm volatile("cp.async.wait_group %0;" :: "n"(N) : "memory");
}
__device__ __forceinline__ void ldm_x4(uint32_t* d, uint32_t addr) {
    asm volatile("ldmatrix.sync.aligned.m8n8.x4.shared.b16 {%0,%1,%2,%3}, [%4];"
                 : "=r"(d[0]), "=r"(d[1]), "=r"(d[2]), "=r"(d[3]) : "r"(addr));
}
__device__ __forceinline__ void mma_f16(float* c, const uint32_t* a, const uint32_t* b) {
    asm volatile(
        "mma.sync.aligned.m16n8k16.row.col.f32.f16.f16.f32 "
        "{%0,%1,%2,%3}, {%4,%5,%6,%7}, {%8,%9}, {%0,%1,%2,%3};"
        : "+f"(c[0]), "+f"(c[1]), "+f"(c[2]), "+f"(c[3])
        : "r"(a[0]), "r"(a[1]), "r"(a[2]), "r"(a[3]), "r"(b[0]), "r"(b[1]));
}
__device__ __forceinline__ float gelu_tanh(float x) {
    return 0.5f * x * (1.f + tanhf(0.7978845608028654f * (x + 0.044715f * x * x * x)));
}
__device__ __forceinline__ int permL(int k, int l) {
    int ll = (k & 2) ? (Ll - 1 - l) : l;
    if (k & 1) ll = (ll % Hh) * Ww + (ll / Hh);
    return ll;
}
// block-wide sum of (s, s2) via warp shuffles; 256 threads; returns via smem bc[0..1]=(mu,inv)
__device__ __forceinline__ void blk_stats(float s, float s2, float invW, float* bc) {
    __shared__ float ps[8], ps2[8];
    const int lane = threadIdx.x & 31, wd = threadIdx.x >> 5;
#pragma unroll
    for (int o = 16; o > 0; o >>= 1) {
        s  += __shfl_xor_sync(0xffffffffu, s, o);
        s2 += __shfl_xor_sync(0xffffffffu, s2, o);
    }
    if (lane == 0) { ps[wd] = s; ps2[wd] = s2; }
    __syncthreads();
    if (threadIdx.x == 0) {
        float ts = 0.f, ts2 = 0.f;
#pragma unroll
        for (int i = 0; i < 8; i++) { ts += ps[i]; ts2 += ps2[i]; }
        const float mu = ts * invW;
        bc[0] = mu;
        bc[1] = rsqrtf(fmaxf(ts2 * invW - mu * mu, 0.f) + 1e-5f);
    }
    __syncthreads();
}

// ---------------- fp16 tensor-core GEMM, templated K-chunk (BK 32 or 64) ----------------
// C[128x128] = A @ (sum_p B_p)^T. NP passes over B. fp32 accum. 256 thr, 2x4 warps, 64x32 tile.
// EPI 0: +bias->fp32  1: +bias+res->fp32  2: gelu(+bias)->fp16  3: +bias->fp16
// EPI 4: +bias+res -> transposed (B,C,L) fp32 out   5: softplus(+bias)->fp16
#define N_STAGES(BK)  ((BK) == 64 ? 3 : 4)
#define GEMM_SMEM_BK(BK) (N_STAGES(BK) * 128 * (BK) * 2 * 2)

template <int BK>
__device__ __forceinline__ uint32_t swz(int row, int c) {
    if (BK == 64) return (uint32_t)(row * 128 + (((c ^ (row & 7))) << 4));
    return (uint32_t)(row * 64 + (((c + (row >> 1)) & 3) << 4));
}

template <int EPI, int NP, int BK>
__global__ __launch_bounds__(256, 2)
void k_gemm(const __half* __restrict__ A,
            const __half* __restrict__ Bhi, const __half* __restrict__ Blo,
            const float* __restrict__ bias, const float* __restrict__ res,
            float* __restrict__ outF, __half* __restrict__ outH,
            int Nn, int Kd, long sA, long sB, long sBias, long sOut) {
    constexpr int CH = BK / 8;
    constexpr int ROWB = BK * 2;
    constexpr int STG = 128 * ROWB;
    constexpr int STAGE = 2 * STG;
    constexpr int NSTG = N_STAGES(BK);
    constexpr int PFD = NSTG - 1;

    extern __shared__ __align__(128) char sm[];
    const int tid = threadIdx.x, lane = tid & 31, wid = tid >> 5;
    const int wm = wid & 1, wn = wid >> 1;
    const int bm = blockIdx.x * 128, bn = blockIdx.y * 128;
    const long kz = blockIdx.z;
    A += kz * sA; Bhi += kz * sB;
    if (bias) bias += kz * sBias;
    if (outH) outH += kz * sOut;
    if (outF) outF += kz * sOut;

    const int nk = Kd / BK, T = NP * nk;
    const __half* pb[2] = {Bhi, Blo};
    const uint32_t smBase = s2u(sm);

    auto issue = [&](int it, int stg) {
        const int p = (NP == 2) ? (it >= nk) : 0;
        const int kc = (it - p * nk) * BK;
        const uint32_t st = smBase + (uint32_t)stg * STAGE;
        const __half* Bp = pb[p];
#pragma unroll
        for (int i = 0; i < 128 * CH / 256; i++) {
            const int g = tid + i * 256;
            const int row = g / CH, c = g % CH;
            const uint32_t sw = swz<BK>(row, c);
            cpasync16(st + sw,       A  + (size_t)(bm + row) * Kd + kc + c * 8);
            cpasync16(st + STG + sw, Bp + (size_t)(bn + row) * Kd + kc + c * 8);
        }
    };

    float acc[4][4][4];
#pragma unroll
    for (int i = 0; i < 4; i++)
#pragma unroll
        for (int j = 0; j < 4; j++)
#pragma unroll
            for (int q = 0; q < 4; q++) acc[i][j][q] = 0.f;

#pragma unroll
    for (int i = 0; i < PFD; i++) { if (i < T) issue(i, i); cpcommit(); }

    int stI = PFD % NSTG, stC = 0;
    for (int it = 0; it < T; it++) {
        cpwaitN<NSTG - 2>();
        __syncthreads();
        if (it + PFD < T) issue(it + PFD, stI);
        cpcommit();
        const uint32_t aB = smBase + (uint32_t)stC * STAGE;
        const uint32_t bB = aB + STG;
#pragma unroll
        for (int s16 = 0; s16 < BK / 16; s16++) {
            uint32_t af[4][4], bf4[2][4];
#pragma unroll
            for (int mi = 0; mi < 4; mi++) {
                const int r = wm * 64 + mi * 16 + (lane & 15);
                const int c = 2 * s16 + (lane >> 4);
                ldm_x4(af[mi], aB + swz<BK>(r, c));
            }
#pragma unroll
            for (int nj = 0; nj < 2; nj++) {
                const int r = wn * 32 + (nj * 2 + (lane >> 4)) * 8 + (lane & 7);
                const int c = 2 * s16 + ((lane >> 3) & 1);
                ldm_x4(bf4[nj], bB + swz<BK>(r, c));
            }
#pragma unroll
            for (int mi = 0; mi < 4; mi++)
#pragma unroll
                for (int nj = 0; nj < 2; nj++) {
                    mma_f16(acc[mi][nj * 2 + 0], af[mi], &bf4[nj][0]);
                    mma_f16(acc[mi][nj * 2 + 1], af[mi], &bf4[nj][2]);
                }
        }
        stI = (stI + 1 == NSTG) ? 0 : stI + 1;
        stC = (stC + 1 == NSTG) ? 0 : stC + 1;
    }

    if (EPI == 4) {
        float* smf = (float*)sm;
        const bool nostrad = (bm % Ll) + 128 <= Ll;
        const int bq0 = bm / Ll, l0 = bm % Ll;
#pragma unroll
        for (int hn = 0; hn < 2; hn++) {
            __syncthreads();
            if ((wn >> 1) == hn) {
#pragma unroll
                for (int mi = 0; mi < 4; mi++)
#pragma unroll
                    for (int ni = 0; ni < 4; ni++) {
                        const int nL = (wn & 1) * 32 + ni * 8 + (lane & 3) * 2;
                        const int n = bn + hn * 64 + nL;
                        const float b0v = __ldg(bias + n), b1v = __ldg(bias + n + 1);
#pragma unroll
                        for (int h = 0; h < 2; h++) {
                            const int mL = wm * 64 + mi * 16 + (lane >> 2) + h * 8;
                            const int m = bm + mL;
                            const float2 rv = *(const float2*)(res + (size_t)m * Nn + n);
                            smf[nL * 132 + mL]       = acc[mi][ni][h * 2 + 0] + b0v + rv.x;
                            smf[(nL + 1) * 132 + mL] = acc[mi][ni][h * 2 + 1] + b1v + rv.y;
                        }
                    }
            }
            __syncthreads();
#pragma unroll
            for (int j = 0; j < 8; j++) {
                const int nr = wid * 8 + j;
                const int ng = bn + hn * 64 + nr;
                const float4 v = *(const float4*)&smf[nr * 132 + lane * 4];
                if (nostrad) {
                    *(float4*)&outF[((size_t)bq0 * Cc + ng) * Ll + l0 + lane * 4] = v;
                } else {
                    const float vv[4] = {v.x, v.y, v.z, v.w};
#pragma unroll
                    for (int q = 0; q < 4; q++) {
                        const int m = bm + lane * 4 + q;
                        outF[((size_t)(m / Ll) * Cc + ng) * Ll + (m % Ll)] = vv[q];
                    }
                }
            }
        }
        return;
    }

#pragma unroll
    for (int mi = 0; mi < 4; mi++) {
#pragma unroll
        for (int ni = 0; ni < 4; ni++) {
            const int n = bn + wn * 32 + ni * 8 + (lane & 3) * 2;
            const float b0v = bias ? __ldg(bias + n) : 0.f;
            const float b1v = bias ? __ldg(bias + n + 1) : 0.f;
#pragma unroll
            for (int h = 0; h < 2; h++) {
                const int m = bm + wm * 64 + mi * 16 + (lane >> 2) + h * 8;
                float v0 = acc[mi][ni][h * 2 + 0] + b0v;
                float v1 = acc[mi][ni][h * 2 + 1] + b1v;
                if (EPI == 1) {
                    const float2 rv = *(const float2*)(res + (size_t)m * Nn + n);
                    v0 += rv.x; v1 += rv.y;
                }
                if (EPI == 2) { v0 = gelu_tanh(v0); v1 = gelu_tanh(v1); }
                if (EPI == 5) {
                    v0 = (v0 > 20.f) ? v0 : log1pf(__expf(v0));
                    v1 = (v1 > 20.f) ? v1 : log1pf(__expf(v1));
                }
                if (EPI == 2 || EPI == 3 || EPI == 5) {
                    __half2 hp; hp.x = __float2half(v0); hp.y = __float2half(v1);
                    *(__half2*)(outH + (size_t)m * Nn + n) = hp;
                } else {
                    *(float2*)(outF + (size_t)m * Nn + n) = make_float2(v0, v1);
                }
            }
        }
    }
}

// ---------------- fused: xt = sum of 3 p2t inputs (fp32 out) + LN1 -> fp16 h ----------------
__global__ void k_fuseln(const float* __restrict__ x1, const float* __restrict__ x2,
                         const float* __restrict__ x3, const float* __restrict__ w,
                         const float* __restrict__ bvec,
                         float* __restrict__ xt, __half* __restrict__ ho) {
    __shared__ float t[Cc * 9];
    const int blk = blockIdx.x;
    const int b = blk / (Ll / 8);
    const int l0 = (blk % (Ll / 8)) * 8;
    const int tid = threadIdx.x;

#pragma unroll
    for (int p = 0; p < 4; p++) {
        const int idx = tid + p * 256;
        const int c = idx >> 1, half = idx & 1;
        const size_t g = ((size_t)b * Cc + c) * Ll + l0 + half * 4;
        const float4 a = *(const float4*)(x1 + g);
        const float4 b2 = *(const float4*)(x2 + g);
        const float4 c2 = *(const float4*)(x3 + g);
        float* dst = t + c * 9 + half * 4;
        dst[0] = a.x + b2.x + c2.x;
        dst[1] = a.y + b2.y + c2.y;
        dst[2] = a.z + b2.z + c2.z;
        dst[3] = a.w + b2.w + c2.w;
    }
    __syncthreads();

    const int lane = tid & 31, wd = tid >> 5;
    float v[16];
    float s = 0.f, s2 = 0.f;
#pragma unroll
    for (int i = 0; i < 16; i++) {
        const int c = lane + i * 32;
        v[i] = t[c * 9 + wd];
        s += v[i]; s2 += v[i] * v[i];
    }
#pragma unroll
    for (int o = 16; o > 0; o >>= 1) {
        s  += __shfl_xor_sync(0xffffffffu, s, o);
        s2 += __shfl_xor_sync(0xffffffffu, s2, o);
    }
    const float mu = s * (1.f / Cc);
    const float inv = rsqrtf(fmaxf(s2 * (1.f / Cc) - mu * mu, 0.f) + 1e-5f);

    const size_t row = (size_t)b * Ll + l0 + wd;
#pragma unroll
    for (int i = 0; i < 16; i++) {
        const int c = lane + i * 32;
        xt[row * Cc + c] = v[i];
        ho[row * Cc + c] = __float2half((v[i] - mu) * inv * w[c] + bvec[c]);
    }
}

// ---------------- LayerNorm(512) -> fp16 (256 threads, shuffle reduction) ----------------
__global__ void k_ln_h(const float* __restrict__ in, const float* __restrict__ w,
                       const float* __restrict__ bvec, __half* __restrict__ ho) {
    __shared__ float bc[2];
    const size_t row = blockIdx.x;
    const float* x = in + row * Cc;
    const int tid = threadIdx.x;

    const float a0 = x[tid], a1 = x[tid + 256];
    blk_stats(a0 + a1, a0 * a0 + a1 * a1, 1.f / Cc, bc);
    const float mu = bc[0], inv = bc[1];

    ho[row * Cc + tid]       = __float2half((a0 - mu) * inv * w[tid] + bvec[tid]);
    ho[row * Cc + tid + 256] = __float2half((a1 - mu) * inv * w[tid + 256] + bvec[tid + 256]);
}

// ---------------- all weight conversions in one kernel ----------------
constexpr int WN1 = 2 * Dd * Cc;
constexpr int WN2 = WN1 + Cc * Dd;
constexpr int WN3 = WN2 + MH * Cc;
constexpr int WN4 = WN3 + Cc * MH;
constexpr int WN5 = WN4 + Kk * Dd * Rr;
constexpr int WN6 = WN5 + 9 * Dd;
constexpr int WN7 = WN6 + XDP * Dd;

__global__ void k_wconv(const float* __restrict__ wip, const float* __restrict__ wop,
                        const float* __restrict__ wf1, const float* __restrict__ wf2,
                        const float* __restrict__ wdt, const float* __restrict__ cw,
                        const float* __restrict__ wxp) {
    const int i = blockIdx.x * 256 + threadIdx.x;
    __half* HB = g_hh;
    if (i < WN1) HB[HH_WIP + i] = __float2half(wip[i]);
    else if (i < WN2) HB[HH_WOP + (i - WN1)] = __float2half(wop[i - WN1]);
    else if (i < WN3) HB[HH_WF1 + (i - WN2)] = __float2half(wf1[i - WN2]);
    else if (i < WN4) HB[HH_WF2 + (i - WN3)] = __float2half(wf2[i - WN3]);
    else if (i < WN5) HB[HH_WDT + (i - WN4)] = __float2half(wdt[i - WN4]);
    else if (i < WN6) {
        const int j = (i - WN5) / Dd, d = (i - WN5) % Dd;
        BUF(OFF_CONVWT)[i - WN5] = cw[(size_t)d * 9 + j];
    } else if (i < WN7) {
        const int j = i - WN6;
        const int row = j >> 10;
        HB[HH_WXP + j] = (row < 160) ? __float2half(wxp[j]) : __float2half(0.f);
    }
}

// ---------------- depthwise 3x3 conv + SiLU (128 thr x 8 d, uint4 loads) ----------------
__global__ __launch_bounds__(128, 10)
void k_conv(const float* __restrict__ conv_b, const __half* __restrict__ xz,
            __half* __restrict__ xc) {
    const int bl = blockIdx.x;
    const int d = threadIdx.x * 8;          // 16B-aligned in fp16
    const int b = bl / Ll, l = bl % Ll;
    const int h = l / Ww, w = l % Ww;
    const float* cw = BUF(OFF_CONVWT);

    float acc[8];
    {
        const float4 b0 = *(const float4*)(conv_b + d);
        const float4 b1 = *(const float4*)(conv_b + d + 4);
        acc[0] = b0.x; acc[1] = b0.y; acc[2] = b0.z; acc[3] = b0.w;
        acc[4] = b1.x; acc[5] = b1.y; acc[6] = b1.z; acc[7] = b1.w;
    }
    const __half* base = xz + (size_t)b * Ll * 2 * Dd + d;
    const bool interior = (h > 0 && h < Hh - 1 && w > 0 && w < Ww - 1);

#pragma unroll
    for (int kh = -1; kh <= 1; kh++) {
        const int hh = h + kh;
        if (!interior && (hh < 0 || hh >= Hh)) continue;
#pragma unroll
        for (int kw = -1; kw <= 1; kw++) {
            const int ww2 = w + kw;
            if (!interior && (ww2 < 0 || ww2 >= Ww)) continue;
            const uint4 raw = *(const uint4*)(base + (size_t)(hh * Ww + ww2) * 2 * Dd);
            const __half2* hp = (const __half2*)&raw;
            const int wi = ((kh + 1) * 3 + kw + 1) * Dd + d;
            const float4 w0 = *(const float4*)(cw + wi);
            const float4 w1 = *(const float4*)(cw + wi + 4);
            const float2 v0 = __half22float2(hp[0]);
            const float2 v1 = __half22float2(hp[1]);
            const float2 v2 = __half22float2(hp[2]);
            const float2 v3 = __half22float2(hp[3]);
            acc[0] += v0.x * w0.x; acc[1] += v0.y * w0.y;
            acc[2] += v1.x * w0.z; acc[3] += v1.y * w0.w;
            acc[4] += v2.x * w1.x; acc[5] += v2.y * w1.y;
            acc[6] += v3.x * w1.z; acc[7] += v3.y * w1.w;
        }
    }
    uint4 oraw;
    __half2* op = (__half2*)&oraw;
#pragma unroll
    for (int i = 0; i < 4; i++) {
        const float a0 = acc[i * 2]     / (1.f + __expf(-acc[i * 2]));
        const float a1 = acc[i * 2 + 1] / (1.f + __expf(-acc[i * 2 + 1]));
        __half2 o; o.x = __float2half(a0); o.y = __float2half(a1);
        op[i] = o;
    }
    *(uint4*)(xc + (size_t)bl * Dd + d) = oraw;
}

// ---------------- gather dt-GEMM A operand ----------------
__global__ void k_adt(__half* __restrict__ adt) {
    const int idx = blockIdx.x * 256 + threadIdx.x;
    const int k = idx / (BL * Rr);
    const int rem = idx % (BL * Rr);
    const int bl = rem >> 5, r = rem & 31;
    const int b = bl / Ll, l = bl % Ll;
    const int pl = permL(k, l);
    adt[idx] = __float2half(BUF(OFF_XDBL)[((size_t)b * Ll + pl) * XDP + k * 40 + r]);
}

// ---------------- selective scan (fp16 u/dt/ys, fp32 state, 1-exp fast path) ----------------
__global__ void k_scan(const float* __restrict__ A_logs, const float* __restrict__ Ds,
                       const __half* __restrict__ xcg, const __half* __restrict__ dtsg,
                       __half* __restrict__ ysg) {
    const int blk = blockIdx.x;
    const int dc = blk & 3;
    const int kb = blk >> 2;
    const int b = kb % Bb;
    const int k = kb / Bb;
    const int d = dc * 256 + threadIdx.x;

    float Aa[Nst];
#pragma unroll
    for (int n = 0; n < Nst; n++) Aa[n] = -__expf(A_logs[((size_t)k * Dd + d) * Nst + n]);
    const float Dv = Ds[k * Dd + d];
    const float a0 = Aa[0];

    bool fast = true;
#pragma unroll
    for (int n = 1; n < Nst; n++)
        fast = fast && (fabsf(Aa[n] - (float)(n + 1) * a0) <= 1e-5f * (float)(n + 1) * fabsf(a0));

    const __half* xc = xcg + (size_t)b * Ll * Dd + d;
    const __half* dts = dtsg + ((size_t)k * BL + (size_t)b * Ll) * Dd + d;
    const float* xd = BUF(OFF_XDBL) + (size_t)b * Ll * XDP + k * 40 + Rr;
    __half* ys = ysg + ((size_t)k * BL + (size_t)b * Ll) * Dd + d;

    float hst[Nst] = {0.f, 0.f, 0.f, 0.f};
    if (fast) {
        for (int l = 0; l < Ll; l++) {
            const int pl = permL(k, l);
            const float u = __half2float(xc[(size_t)pl * Dd]);
            const float dt = __half2float(dts[(size_t)l * Dd]);
            const float4 Bv = *(const float4*)(xd + (size_t)pl * XDP);
            const float4 Cv = *(const float4*)(xd + (size_t)pl * XDP + 4);
            const float du = dt * u;
            const float e1 = __expf(dt * a0);
            const float e2 = e1 * e1;
            hst[0] = hst[0] * e1        + du * Bv.x;
            hst[1] = hst[1] * e2        + du * Bv.y;
            hst[2] = hst[2] * (e2 * e1) + du * Bv.z;
            hst[3] = hst[3] * (e2 * e2) + du * Bv.w;
            const float y = hst[0] * Cv.x + hst[1] * Cv.y + hst[2] * Cv.z + hst[3] * Cv.w;
            ys[(size_t)l * Dd] = __float2half(y + Dv * u);
        }
    } else {
        for (int l = 0; l < Ll; l++) {
            const int pl = permL(k, l);
            const float u = __half2float(xc[(size_t)pl * Dd]);
            const float dt = __half2float(dts[(size_t)l * Dd]);
            const float4 Bv = *(const float4*)(xd + (size_t)pl * XDP);
            const float4 Cv = *(const float4*)(xd + (size_t)pl * XDP + 4);
            const float du = dt * u;
            const float bArr[4] = {Bv.x, Bv.y, Bv.z, Bv.w};
            const float cArr[4] = {Cv.x, Cv.y, Cv.z, Cv.w};
            float y = 0.f;
#pragma unroll
            for (int n = 0; n < Nst; n++) {
                const float dA = __expf(dt * Aa[n]);
                hst[n] = hst[n] * dA + du * bArr[n];
                y += hst[n] * cArr[n];
            }
            ys[(size_t)l * Dd] = __float2half(y + Dv * u);
        }
    }
}

// ---------------- cross-merge + out_norm LN + SiLU gate (256 thr, half2) ----------------
__global__ void k_merge(const float* __restrict__ onw, const float* __restrict__ onb,
                        const __half* __restrict__ ys, const __half* __restrict__ xz,
                        __half* __restrict__ yg) {
    __shared__ float bufr[Dd];
    __shared__ float bc[2];
    const int bl = blockIdx.x;
    const int b = bl / Ll, l = bl % Ll;
    const int h = l / Ww, w = l % Ww;
    const int lt = w * Hh + h;
    const int tid = threadIdx.x;

    const size_t r0 = (((size_t)(0 * Bb + b)) * Ll + l) * Dd;
    const size_t r1 = (((size_t)(1 * Bb + b)) * Ll + lt) * Dd;
    const size_t r2 = (((size_t)(2 * Bb + b)) * Ll + (Ll - 1 - l)) * Dd;
    const size_t r3 = (((size_t)(3 * Bb + b)) * Ll + (Ll - 1 - lt)) * Dd;

    float s = 0.f, s2 = 0.f;
#pragma unroll
    for (int it = 0; it < 2; it++) {
        const int d = (tid + it * 256) * 2;
        const float2 v0 = __half22float2(*(const __half2*)(ys + r0 + d));
        const float2 v1 = __half22float2(*(const __half2*)(ys + r1 + d));
        const float2 v2 = __half22float2(*(const __half2*)(ys + r2 + d));
        const float2 v3 = __half22float2(*(const __half2*)(ys + r3 + d));
        const float a = v0.x + v1.x + v2.x + v3.x;
        const float bb2 = v0.y + v1.y + v2.y + v3.y;
        bufr[d] = a; bufr[d + 1] = bb2;
        s += a + bb2; s2 += a * a + bb2 * bb2;
    }
    blk_stats(s, s2, 1.f / Dd, bc);
    const float mu = bc[0], inv = bc[1];

#pragma unroll
    for (int it = 0; it < 2; it++) {
        const int d = (tid + it * 256) * 2;
        const float2 zv = __half22float2(*(const __half2*)(xz + (size_t)bl * 2 * Dd + Dd + d));
        const float g0 = zv.x / (1.f + __expf(-zv.x));
        const float g1 = zv.y / (1.f + __expf(-zv.y));
        __half2 o;
        o.x = __float2half(((bufr[d] - mu) * inv * onw[d] + onb[d]) * g0);
        o.y = __float2half(((bufr[d + 1] - mu) * inv * onw[d + 1] + onb[d + 1]) * g1);
        *(__half2*)(yg + (size_t)bl * Dd + d) = o;
    }
}

// ---------------- launch ----------------
extern "C" void kernel_launch(void* const* d_in, const int* in_sizes, int n_in,
                              void* d_out, int out_size) {
    const float* x1        = (const float*)d_in[0];
    const float* x2        = (const float*)d_in[1];
    const float* x3        = (const float*)d_in[2];
    const float* ln1_w     = (const float*)d_in[3];
    const float* ln1_b     = (const float*)d_in[4];
    const float* in_proj_w = (const float*)d_in[5];
    const float* in_proj_b = (const float*)d_in[6];
    const float* conv_w    = (const float*)d_in[7];
    const float* conv_b    = (const float*)d_in[8];
    const float* x_proj_w  = (const float*)d_in[9];
    const float* dt_w      = (const float*)d_in[10];
    const float* dt_b      = (const float*)d_in[11];
    const float* A_logs    = (const float*)d_in[12];
    const float* Ds        = (const float*)d_in[13];
    const float* out_norm_w= (const float*)d_in[14];
    const float* out_norm_b= (const float*)d_in[15];
    const float* out_proj_w= (const float*)d_in[16];
    const float* out_proj_b= (const float*)d_in[17];
    const float* ln2_w     = (const float*)d_in[18];
    const float* ln2_b     = (const float*)d_in[19];
    const float* fc1_w     = (const float*)d_in[20];
    const float* fc1_b     = (const float*)d_in[21];
    const float* fc2_w     = (const float*)d_in[22];
    const float* fc2_b     = (const float*)d_in[23];
    float* out = (float*)d_out;

    void* pf = nullptr;  cudaGetSymbolAddress(&pf, g_buf);
    void* ph = nullptr;  cudaGetSymbolAddress(&ph, g_hh);
    float* F = (float*)pf;
    __half* HB = (__half*)ph;

    constexpr int SM64 = GEMM_SMEM_BK(64);
    constexpr int SM32 = GEMM_SMEM_BK(32);

    static bool attr_done = false;
    if (!attr_done) {
        cudaFuncSetAttribute(k_gemm<0, 1, 64>, cudaFuncAttributeMaxDynamicSharedMemorySize, SM64);
        cudaFuncSetAttribute(k_gemm<1, 1, 64>, cudaFuncAttributeMaxDynamicSharedMemorySize, SM64);
        cudaFuncSetAttribute(k_gemm<2, 1, 64>, cudaFuncAttributeMaxDynamicSharedMemorySize, SM64);
        cudaFuncSetAttribute(k_gemm<3, 1, 64>, cudaFuncAttributeMaxDynamicSharedMemorySize, SM64);
        cudaFuncSetAttribute(k_gemm<4, 1, 64>, cudaFuncAttributeMaxDynamicSharedMemorySize, SM64);
        cudaFuncSetAttribute(k_gemm<5, 1, 32>, cudaFuncAttributeMaxDynamicSharedMemorySize, SM32);
        attr_done = true;
    }

    // 1. all weight conversions
    k_wconv<<<(WN7 + 255) / 256, 256>>>(in_proj_w, out_proj_w, fc1_w, fc2_w, dt_w, conv_w, x_proj_w);
    // 2. fused 3-way fuse + LN1 -> xt fp32, h fp16
    k_fuseln<<<BL / 8, 256>>>(x1, x2, x3, ln1_w, ln1_b, F + OFF_XT, HB + HH_H);
    // 3. in_proj -> xz fp16
    k_gemm<3, 1, 64><<<dim3(BL / 128, 2 * Dd / 128), 256, SM64>>>(
        HB + HH_H, HB + HH_WIP, nullptr, in_proj_b, nullptr,
        nullptr, HB + HH_XZ, 2 * Dd, Cc, 0, 0, 0, 0);
    // 4. conv + silu -> xc fp16
    k_conv<<<BL, 128>>>(conv_b, HB + HH_XZ, HB + HH_XC);
    // 5. x_proj (single pass) -> xd fp32 [BL,256]
    k_gemm<0, 1, 64><<<dim3(BL / 128, XDP / 128), 256, SM64>>>(
        HB + HH_XC, HB + HH_WXP, nullptr, nullptr, nullptr,
        F + OFF_XDBL, nullptr, XDP, Dd, 0, 0, 0, 0);
    // 6. gather dt GEMM A operands
    k_adt<<<(Kk * BL * Rr) / 256, 256>>>(HB + HH_ADT);
    // 7. dt projection (batched): softplus(adt_k @ dt_w_k^T + dt_b_k)
    k_gemm<5, 1, 32><<<dim3(BL / 128, Dd / 128, Kk), 256, SM32>>>(
        HB + HH_ADT, HB + HH_WDT, nullptr, dt_b, nullptr,
        nullptr, HB + HH_DTS, Dd, Rr,
        (long)BL * Rr, (long)Dd * Rr, (long)Dd, (long)BL * Dd);
    // 8. selective scan -> ys fp16
    k_scan<<<Kk * Bb * 4, 256>>>(A_logs, Ds, HB + HH_XC, HB + HH_DTS, HB + HH_YS);
    // 9. merge + LN + gate -> yg fp16
    k_merge<<<BL, 256>>>(out_norm_w, out_norm_b, HB + HH_YS, HB + HH_XZ, HB + HH_YG);
    // 10. out_proj + residual(xt) -> xres fp32
    k_gemm<1, 1, 64><<<dim3(BL / 128, Cc / 128), 256, SM64>>>(
        HB + HH_YG, HB + HH_WOP, nullptr, out_proj_b, F + OFF_XT,
        F + OFF_XRES, nullptr, Cc, Dd, 0, 0, 0, 0);
    // 11. LN2 -> fp16
    k_ln_h<<<BL, 256>>>(F + OFF_XRES, ln2_w, ln2_b, HB + HH_M1);
    // 12. fc1 + gelu -> mh fp16
    k_gemm<2, 1, 64><<<dim3(BL / 128, MH / 128), 256, SM64>>>(
        HB + HH_M1, HB + HH_WF1, nullptr, fc1_b, nullptr,
        nullptr, HB + HH_MH, MH, Cc, 0, 0, 0, 0);
    // 13. fc2 + residual(xres) -> direct (B,C,H,W) output (fused token2patch)
    k_gemm<4, 1, 64><<<dim3(BL / 128, Cc / 128), 256, SM64>>>(
        HB + HH_MH, HB + HH_WF2, nullptr, fc2_b, F + OFF_XRES,
        out, nullptr, Cc, MH, 0, 0, 0, 0);
}